// round 8
// baseline (speedup 1.0000x reference)
#include <cuda_runtime.h>
#include <cuda_bf16.h>

#define B_   32
#define C1   1024
#define C2   256
#define C3   64
#define T_   2048
#define EPSV 1e-5f
#define MUHALF ((size_t)B_ * 32 * T_)
#define S1   8
#define S2   8

// ---- gemm1 tiling: BM=256 (all M), BN=64, BK=32, 512 threads, persistent ----
#define NTIL   1024            /* 32 batches x 32 n-tiles(64) */
#define KIT    32              /* C1 / 32 */
#define ST_SZ  49152           /* 48KB: Wh 16K | Wl 16K | Xf 16K(8K used pad) ... see offsets */
#define NSTG   4
#define G1_SMEM (NSTG * ST_SZ) /* 192KB */
// stage offsets
#define O_WH 0
#define O_WL 16384
#define O_XF 32768             /* 32k x 64n fp32 = 8KB */
#define O_CH 40960             /* 32k x 64n bf16 = 4KB */
#define O_CL 45056             /* 4KB */

// ---- gemm2 ----
#define KIT2 (C2 / 32)
#define G2_STAGE 24576
#define G2_SMEM  (3 * G2_STAGE)

typedef unsigned long long u64;
typedef unsigned int u32;

// ---------------- scratch ------------------------------------------------------
__device__ u32 g_hh[(size_t)B_ * C2 * T_ / 2];          // 32 MB h hi (bf16x2)
__device__ u32 g_hl[(size_t)B_ * C2 * T_ / 2];          // 32 MB h lo
__device__ __nv_bfloat16 g_w1h[C2 * C1], g_w1l[C2 * C1];
__device__ __nv_bfloat16 g_w2h[C3 * C2], g_w2l[C3 * C2];
__device__ float g_b1f[C2], g_b2f[C3];
__device__ float g_ps1[C1 * S1], g_pq1[C1 * S1];
__device__ float g_ps2[C2 * S2], g_pq2[C2 * S2];

// ---------------- helpers ------------------------------------------------------
__device__ __forceinline__ u32 smem_u32(const void* p) {
    u32 a; asm("{ .reg .u64 t; cvta.to.shared.u64 t, %1; cvt.u32.u64 %0, t; }" : "=r"(a) : "l"(p));
    return a;
}
__device__ __forceinline__ void cp16(u32 dst, const void* src) {
    asm volatile("cp.async.cg.shared.global [%0], [%1], 16;" :: "r"(dst), "l"(src));
}
__device__ __forceinline__ void cpcommit() { asm volatile("cp.async.commit_group;" ::: "memory"); }
__device__ __forceinline__ void ldsm4(u32* r, u32 addr) {
    asm volatile("ldmatrix.sync.aligned.m8n8.x4.shared.b16 {%0,%1,%2,%3}, [%4];"
        : "=r"(r[0]), "=r"(r[1]), "=r"(r[2]), "=r"(r[3]) : "r"(addr));
}
__device__ __forceinline__ void ldsm4t(u32* r, u32 addr) {
    asm volatile("ldmatrix.sync.aligned.m8n8.x4.trans.shared.b16 {%0,%1,%2,%3}, [%4];"
        : "=r"(r[0]), "=r"(r[1]), "=r"(r[2]), "=r"(r[3]) : "r"(addr));
}
__device__ __forceinline__ void mma16816(float* d, const u32* a, const u32* b) {
    asm volatile("mma.sync.aligned.m16n8k16.row.col.f32.bf16.bf16.f32 "
        "{%0,%1,%2,%3}, {%4,%5,%6,%7}, {%8,%9}, {%0,%1,%2,%3};"
        : "+f"(d[0]), "+f"(d[1]), "+f"(d[2]), "+f"(d[3])
        : "r"(a[0]), "r"(a[1]), "r"(a[2]), "r"(a[3]), "r"(b[0]), "r"(b[1]));
}
__device__ __forceinline__ void split2(float v0, float v1, u32& h, u32& l) {
    __nv_bfloat162 hh = __floats2bfloat162_rn(v0, v1);
    float r0 = v0 - __bfloat162float(hh.x);
    float r1 = v1 - __bfloat162float(hh.y);
    __nv_bfloat162 ll = __floats2bfloat162_rn(r0, r1);
    h = *(u32*)&hh; l = *(u32*)&ll;
}
__device__ __forceinline__ float4 lds128(u32 addr) {
    float4 v;
    asm volatile("ld.shared.v4.f32 {%0,%1,%2,%3}, [%4];"
        : "=f"(v.x), "=f"(v.y), "=f"(v.z), "=f"(v.w) : "r"(addr));
    return v;
}
__device__ __forceinline__ void sts64(u32 addr, u32 a, u32 b) {
    asm volatile("st.shared.v2.u32 [%0], {%1,%2};" :: "r"(addr), "r"(a), "r"(b));
}

// ---------------- stats1 (pure reduction) ---------------------------------------
__global__ __launch_bounds__(256) void stats1_kernel(const float* __restrict__ x) {
    __shared__ float sh_s[256], sh_q[256];
    const int c = blockIdx.x, sp = blockIdx.y, tid = threadIdx.x;
    float s = 0.f, q = 0.f;
    #pragma unroll
    for (int j = 0; j < 4; j++) {
        const int b = sp * 4 + j;
        const float4* row = (const float4*)(x + ((size_t)b * C1 + c) * T_);
        float4 a0 = row[tid], a1 = row[tid + 256];
        s += a0.x + a0.y + a0.z + a0.w + a1.x + a1.y + a1.z + a1.w;
        q += a0.x*a0.x + a0.y*a0.y + a0.z*a0.z + a0.w*a0.w
           + a1.x*a1.x + a1.y*a1.y + a1.z*a1.z + a1.w*a1.w;
    }
    sh_s[tid] = s; sh_q[tid] = q;
    __syncthreads();
    for (int off = 128; off > 0; off >>= 1) {
        if (tid < off) { sh_s[tid] += sh_s[tid + off]; sh_q[tid] += sh_q[tid + off]; }
        __syncthreads();
    }
    if (tid == 0) { g_ps1[c * S1 + sp] = sh_s[0]; g_pq1[c * S1 + sp] = sh_q[0]; }
}

// ---------------- stats2 on hh/hl ------------------------------------------------
__global__ __launch_bounds__(256) void stats2_part_kernel() {
    __shared__ float sh_s[256], sh_q[256];
    const int c = blockIdx.x, sp = blockIdx.y, tid = threadIdx.x;
    uint4 H[4], L[4];
    #pragma unroll
    for (int j = 0; j < 4; j++) {
        int b = sp * 4 + j;
        size_t rowq = ((size_t)b * C2 + c) * T_ / 8;
        H[j] = ((const uint4*)g_hh)[rowq + tid];
        L[j] = ((const uint4*)g_hl)[rowq + tid];
    }
    float s = 0.f, q = 0.f;
    #pragma unroll
    for (int j = 0; j < 4; j++) {
        u32 hw[4] = {H[j].x, H[j].y, H[j].z, H[j].w};
        u32 lw[4] = {L[j].x, L[j].y, L[j].z, L[j].w};
        #pragma unroll
        for (int k = 0; k < 4; k++) {
            __nv_bfloat162 hb = *(__nv_bfloat162*)&hw[k];
            __nv_bfloat162 lb = *(__nv_bfloat162*)&lw[k];
            float v0 = __bfloat162float(hb.x) + __bfloat162float(lb.x);
            float v1 = __bfloat162float(hb.y) + __bfloat162float(lb.y);
            s += v0 + v1;
            q += v0 * v0 + v1 * v1;
        }
    }
    sh_s[tid] = s; sh_q[tid] = q;
    __syncthreads();
    for (int off = 128; off > 0; off >>= 1) {
        if (tid < off) { sh_s[tid] += sh_s[tid + off]; sh_q[tid] += sh_q[tid + off]; }
        __syncthreads();
    }
    if (tid == 0) { g_ps2[c * S2 + sp] = sh_s[0]; g_pq2[c * S2 + sp] = sh_q[0]; }
}

// ---------------- fold1 (finalize fused) ------------------------------------------
__global__ __launch_bounds__(256) void fold1_kernel(const float* __restrict__ w,
                                                    const float* __restrict__ bias,
                                                    const float* __restrict__ bg,
                                                    const float* __restrict__ bb) {
    __shared__ float sa[C1], sd[C1];
    __shared__ float sh[256];
    const int o = blockIdx.x, tid = threadIdx.x;
    const float inv_n = 1.f / (float)(B_ * T_);
    #pragma unroll
    for (int k = tid; k < C1; k += 256) {
        float s = 0.f, q = 0.f;
        #pragma unroll
        for (int i = 0; i < S1; i++) { s += g_ps1[k * S1 + i]; q += g_pq1[k * S1 + i]; }
        float mean = s * inv_n;
        float var  = q * inv_n - mean * mean;
        float av = bg[k] * rsqrtf(var + EPSV);
        sa[k] = av;
        sd[k] = bb[k] - mean * av;
    }
    __syncthreads();
    float acc = 0.f;
    for (int k = tid; k < C1; k += 256) {
        float wv = w[(size_t)o * C1 + k];
        float wf = wv * sa[k];
        __nv_bfloat16 h = __float2bfloat16(wf);
        g_w1h[(size_t)o * C1 + k] = h;
        g_w1l[(size_t)o * C1 + k] = __float2bfloat16(wf - __bfloat162float(h));
        acc += wv * sd[k];
    }
    sh[tid] = acc;
    __syncthreads();
    for (int off = 128; off > 0; off >>= 1) {
        if (tid < off) sh[tid] += sh[tid + off];
        __syncthreads();
    }
    if (tid == 0) g_b1f[o] = bias[o] + sh[0];
}

// ---------------- fold2 (finalize fused) ------------------------------------------
__global__ __launch_bounds__(256) void fold2_kernel(const float* __restrict__ w,
                                                    const float* __restrict__ bias,
                                                    const float* __restrict__ bg,
                                                    const float* __restrict__ bb) {
    __shared__ float sa[C2], sd[C2];
    __shared__ float sh[256];
    const int o = blockIdx.x, tid = threadIdx.x;
    const float inv_n = 1.f / (float)(B_ * T_);
    if (tid < C2) {
        float s = 0.f, q = 0.f;
        #pragma unroll
        for (int i = 0; i < S2; i++) { s += g_ps2[tid * S2 + i]; q += g_pq2[tid * S2 + i]; }
        float mean = s * inv_n;
        float var  = q * inv_n - mean * mean;
        float av = bg[tid] * rsqrtf(var + EPSV);
        sa[tid] = av;
        sd[tid] = bb[tid] - mean * av;
    }
    __syncthreads();
    float acc = 0.f;
    for (int k = tid; k < C2; k += 256) {
        float wv = w[(size_t)o * C2 + k];
        float wf = wv * sa[k];
        __nv_bfloat16 h = __float2bfloat16(wf);
        g_w2h[(size_t)o * C2 + k] = h;
        g_w2l[(size_t)o * C2 + k] = __float2bfloat16(wf - __bfloat162float(h));
        acc += wv * sd[k];
    }
    sh[tid] = acc;
    __syncthreads();
    for (int off = 128; off > 0; off >>= 1) {
        if (tid < off) sh[tid] += sh[tid + off];
        __syncthreads();
    }
    if (tid == 0) g_b2f[o] = bias[o] + sh[0];
}

// ---------------- GEMM1: persistent, BM256xBN64, fused fp32->bf16 split -----------
extern __shared__ char g1s[];

// issue stage for virtual iter vi (tile = bid + (vi>>5)*grid, k-chunk = vi&31)
__device__ __forceinline__ void g1_issue(u32 sb0, int vi, int grid,
                                         const float* __restrict__ x, int tid) {
    const int ti = blockIdx.x + (vi >> 5) * grid;
    const int b = ti >> 5, n0 = (ti & 31) << 6, k0 = (vi & 31) << 5;
    const u32 sb = sb0 + (vi & 3) * ST_SZ;
    // W: 256 rows x 32k bf16 h/l (16KB each): thread -> 2 chunks of each
    const int m = tid >> 1;
    #pragma unroll
    for (int j = 0; j < 2; j++) {
        int c = (tid & 1) * 2 + j;
        u32 dst = sb + m * 64 + ((c ^ ((m >> 1) & 3)) << 4);
        size_t src = (size_t)m * (C1 / 8) + (k0 >> 3) + c;
        cp16(dst + O_WH, (const uint4*)g_w1h + src);
        cp16(dst + O_WL, (const uint4*)g_w1l + src);
    }
    // X fp32: 32k x 64n = 8KB: thread -> 1 chunk (16B), linear layout
    {
        int k = tid >> 4, c = tid & 15;
        u32 dst = sb + O_XF + k * 256 + c * 16;
        const float* src = x + ((size_t)(b * C1 + k0 + k)) * T_ + n0 + c * 4;
        cp16(dst, src);
    }
    cpcommit();
}

// convert stage (vi): fp32 smem -> bf16 h/l smem (ldsm-B layout, 128B rows)
__device__ __forceinline__ void g1_convert(u32 sb0, int vi, int tid) {
    const u32 sb = sb0 + (vi & 3) * ST_SZ;
    const int k = tid >> 4, c = tid & 15;
    float4 v = lds128(sb + O_XF + k * 256 + c * 16);
    u32 h0, l0, h1, l1;
    split2(v.x, v.y, h0, l0);
    split2(v.z, v.w, h1, l1);
    u32 dst = sb + k * 128 + ((((c >> 1) ^ (k & 7))) << 4) + ((c & 1) << 3);
    sts64(dst + O_CH, h0, h1);
    sts64(dst + O_CL, l0, l1);
}

__global__ __launch_bounds__(512, 1) void gemm1_kernel(const float* __restrict__ x, int grid) {
    const int tid = threadIdx.x, lane = tid & 31, wid = tid >> 5;
    const int wm = (wid & 7) * 32, wn = (wid >> 3) * 32;   // 8 m-warps x 2 n-warps
    const u32 sb0 = smem_u32(g1s);

    const int ntile = (NTIL - blockIdx.x + grid - 1) / grid;
    const int tot = ntile * KIT;

    float acc[2][4][4];
    #pragma unroll
    for (int mi = 0; mi < 2; mi++)
        #pragma unroll
        for (int nj = 0; nj < 4; nj++)
            #pragma unroll
            for (int r = 0; r < 4; r++) acc[mi][nj][r] = 0.f;

    g1_issue(sb0, 0, grid, x, tid);
    g1_issue(sb0, 1, grid, x, tid);
    g1_issue(sb0, 2, grid, x, tid);
    asm volatile("cp.async.wait_group 2;" ::: "memory");
    __syncthreads();
    g1_convert(sb0, 0, tid);

    #pragma unroll 1
    for (int vi = 0; vi < tot; vi++) {
        if (vi + 2 < tot) asm volatile("cp.async.wait_group 1;" ::: "memory");
        else              asm volatile("cp.async.wait_group 0;" ::: "memory");
        __syncthreads();
        if (vi + 3 < tot) g1_issue(sb0, vi + 3, grid, x, tid);
        if (vi + 1 < tot) g1_convert(sb0, vi + 1, tid);

        const u32 sb = sb0 + (vi & 3) * ST_SZ;
        #pragma unroll
        for (int ks = 0; ks < 2; ks++) {
            u32 ah[2][4], al[2][4];
            #pragma unroll
            for (int mi = 0; mi < 2; mi++) {
                int ml = wm + mi * 16 + (lane & 15);
                int kk = ks * 16 + (lane >> 4) * 8;
                u32 a_addr = sb + ml * 64 + (((kk >> 3) ^ ((ml >> 1) & 3)) << 4);
                ldsm4(ah[mi], a_addr + O_WH);
                ldsm4(al[mi], a_addr + O_WL);
            }
            const int mat = lane >> 3, rr = lane & 7;
            #pragma unroll
            for (int nb = 0; nb < 2; nb++) {
                int kk = ks * 16 + (mat & 1) * 8 + rr;
                int nn = wn + nb * 16 + (mat >> 1) * 8;
                u32 b_addr = sb + kk * 128 + (((nn >> 3) ^ (kk & 7)) << 4);
                u32 bh[4], bl[4];
                ldsm4t(bh, b_addr + O_CH);
                ldsm4t(bl, b_addr + O_CL);
                #pragma unroll
                for (int mi = 0; mi < 2; mi++) {
                    mma16816(acc[mi][2*nb],     ah[mi], bh);
                    mma16816(acc[mi][2*nb],     ah[mi], bl);
                    mma16816(acc[mi][2*nb],     al[mi], bh);
                    mma16816(acc[mi][2*nb + 1], ah[mi], bh + 2);
                    mma16816(acc[mi][2*nb + 1], ah[mi], bl + 2);
                    mma16816(acc[mi][2*nb + 1], al[mi], bh + 2);
                }
            }
        }

        if ((vi & 31) == 31) {
            // epilogue for the finished tile
            const int ti = blockIdx.x + (vi >> 5) * grid;
            const int b = ti >> 5, n0 = (ti & 31) << 6;
            const int g = lane >> 2, q = lane & 3;
            #pragma unroll
            for (int mi = 0; mi < 2; mi++) {
                #pragma unroll
                for (int rw = 0; rw < 2; rw++) {
                    const int m = wm + mi * 16 + g + rw * 8;
                    const float bias = g_b1f[m];
                    size_t rowu = (((size_t)b * C2 + m) * T_ + n0 + wn) / 2;
                    #pragma unroll
                    for (int nj = 0; nj < 4; nj++) {
                        float v0 = fmaxf(acc[mi][nj][rw * 2 + 0] + bias, 0.f);
                        float v1 = fmaxf(acc[mi][nj][rw * 2 + 1] + bias, 0.f);
                        u32 h, l;
                        split2(v0, v1, h, l);
                        g_hh[rowu + nj * 4 + q] = h;
                        g_hl[rowu + nj * 4 + q] = l;
                    }
                }
            }
            #pragma unroll
            for (int mi = 0; mi < 2; mi++)
                #pragma unroll
                for (int nj = 0; nj < 4; nj++)
                    #pragma unroll
                    for (int r = 0; r < 4; r++) acc[mi][nj][r] = 0.f;
        }
    }
}

// ---------------- GEMM2: cp.async 3-stage, mma bf16 3-term -------------------------
extern __shared__ char g2s[];

__device__ __forceinline__ void g2_issue(u32 sb, int it, int n0, int b, int tid) {
    const int k0 = it * 32;
    {
        int row = tid >> 2, c = tid & 3;
        u32 dst = sb + row * 64 + ((c ^ ((row >> 1) & 3)) << 4);
        size_t src = (size_t)row * (C2 / 8) + (k0 >> 3) + c;
        cp16(dst,        (const uint4*)g_w2h + src);
        cp16(dst + 4096, (const uint4*)g_w2l + src);
    }
    #pragma unroll
    for (int j = 0; j < 2; j++) {
        int u = tid + j * 256;
        int row = u >> 4, c = u & 15;
        u32 dst = sb + 8192 + row * 256 + ((c ^ (row & 7)) << 4);
        size_t src = (((size_t)(b * C2 + k0 + row)) * T_ + n0) / 8 + c;
        cp16(dst,        (const uint4*)g_hh + src);
        cp16(dst + 8192, (const uint4*)g_hl + src);
    }
    cpcommit();
}

__global__ __launch_bounds__(256, 2) void gemm2_kernel(float* __restrict__ out) {
    const int tid = threadIdx.x, lane = tid & 31, wid = tid >> 5;
    const int b = blockIdx.z, n0 = blockIdx.x * 128;
    const int wm = (wid & 1) * 32, wn = (wid >> 1) * 32;
    const u32 sb0 = smem_u32(g2s);

    float acc[2][4][4];
    #pragma unroll
    for (int mi = 0; mi < 2; mi++)
        #pragma unroll
        for (int nj = 0; nj < 4; nj++)
            #pragma unroll
            for (int r = 0; r < 4; r++) acc[mi][nj][r] = 0.f;

    g2_issue(sb0,            0, n0, b, tid);
    g2_issue(sb0 + G2_STAGE, 1, n0, b, tid);

    #pragma unroll 1
    for (int it = 0; it < KIT2; it++) {
        if (it < KIT2 - 1) asm volatile("cp.async.wait_group 1;" ::: "memory");
        else               asm volatile("cp.async.wait_group 0;" ::: "memory");
        __syncthreads();
        if (it + 2 < KIT2) {
            int sl = it + 2 - ((it + 2) / 3) * 3;
            g2_issue(sb0 + sl * G2_STAGE, it + 2, n0, b, tid);
        }
        const u32 Bbase = sb0 + (it - (it / 3) * 3) * G2_STAGE;
        #pragma unroll
        for (int ks = 0; ks < 2; ks++) {
            u32 ah[2][4], al[2][4];
            #pragma unroll
            for (int mi = 0; mi < 2; mi++) {
                int ml = wm + mi * 16 + (lane & 15);
                int kk = ks * 16 + (lane >> 4) * 8;
                u32 a_addr = Bbase + ml * 64 + (((kk >> 3) ^ ((ml >> 1) & 3)) << 4);
                ldsm4(ah[mi], a_addr);
                ldsm4(al[mi], a_addr + 4096);
            }
            const int mat = lane >> 3, rr = lane & 7;
            #pragma unroll
            for (int nbk = 0; nbk < 2; nbk++) {
                int kk = ks * 16 + (mat & 1) * 8 + rr;
                int nn = wn + nbk * 16 + (mat >> 1) * 8;
                u32 b_addr = Bbase + 8192 + kk * 256 + (((nn >> 3) ^ (kk & 7)) << 4);
                u32 bh[4], bl[4];
                ldsm4t(bh, b_addr);
                ldsm4t(bl, b_addr + 8192);
                #pragma unroll
                for (int mi = 0; mi < 2; mi++) {
                    mma16816(acc[mi][2*nbk],     ah[mi], bh);
                    mma16816(acc[mi][2*nbk],     ah[mi], bl);
                    mma16816(acc[mi][2*nbk],     al[mi], bh);
                    mma16816(acc[mi][2*nbk + 1], ah[mi], bh + 2);
                    mma16816(acc[mi][2*nbk + 1], ah[mi], bl + 2);
                    mma16816(acc[mi][2*nbk + 1], al[mi], bh + 2);
                }
            }
        }
    }

    const int g = lane >> 2, q = lane & 3;
    #pragma unroll
    for (int mi = 0; mi < 2; mi++) {
        #pragma unroll
        for (int rw = 0; rw < 2; rw++) {
            const int o = wm + mi * 16 + g + rw * 8;
            const float bias = g_b2f[o];
            const size_t base = (o < 32)
                ? ((size_t)b * 32 * T_ + (size_t)o * T_)
                : (MUHALF + (size_t)b * 32 * T_ + (size_t)(o - 32) * T_);
            #pragma unroll
            for (int nj = 0; nj < 4; nj++) {
                float2 v;
                v.x = acc[mi][nj][rw * 2 + 0] + bias;
                v.y = acc[mi][nj][rw * 2 + 1] + bias;
                *(float2*)(out + base + n0 + wn + nj * 8 + q * 2) = v;
            }
        }
    }
}

// ---------------- launcher ---------------------------------------------------------
extern "C" void kernel_launch(void* const* d_in, const int* in_sizes, int n_in,
                              void* d_out, int out_size) {
    const float* x     = (const float*)d_in[0];
    const float* bn1_g = (const float*)d_in[1];
    const float* bn1_b = (const float*)d_in[2];
    const float* w1    = (const float*)d_in[3];
    const float* b1    = (const float*)d_in[4];
    const float* bn2_g = (const float*)d_in[5];
    const float* bn2_b = (const float*)d_in[6];
    const float* w2    = (const float*)d_in[7];
    const float* b2    = (const float*)d_in[8];
    float* out = (float*)d_out;

    int sms = 148;
    cudaDeviceGetAttribute(&sms, cudaDevAttrMultiProcessorCount, 0);
    if (sms <= 0 || sms > NTIL) sms = 148;

    cudaFuncSetAttribute(gemm1_kernel, cudaFuncAttributeMaxDynamicSharedMemorySize, G1_SMEM);
    cudaFuncSetAttribute(gemm2_kernel, cudaFuncAttributeMaxDynamicSharedMemorySize, G2_SMEM);

    stats1_kernel<<<dim3(C1, S1), 256>>>(x);
    fold1_kernel<<<C2, 256>>>(w1, b1, bn1_g, bn1_b);
    gemm1_kernel<<<sms, 512, G1_SMEM>>>(x, sms);
    stats2_part_kernel<<<dim3(C2, S2), 256>>>();
    fold2_kernel<<<C3, 256>>>(w2, b2, bn2_g, bn2_b);
    gemm2_kernel<<<dim3(T_ / 128, 1, B_), 256, G2_SMEM>>>(out);
}

// round 9
// speedup vs baseline: 1.2510x; 1.2510x over previous
#include <cuda_runtime.h>
#include <cuda_bf16.h>

#define B_   32
#define C1   1024
#define C2   256
#define C3   64
#define T_   2048
#define EPSV 1e-5f
#define MUHALF ((size_t)B_ * 32 * T_)
#define S1   8
#define S2   8

#define BM 128
#define BN 128
#define BK 32
#define KIT  (C1 / BK)          /* 32 */
#define KIT2 (C2 / BK)          /* 8  */

// gemm1 smem rings (per CTA, dynamic): W 3-ring | Xf 2-ring | Xc 2-ring
#define O_W    0                /* 3 x 16KB  (Wh 8K | Wl 8K) */
#define O_XF   49152            /* 2 x 16KB  fp32 X          */
#define O_XC   81920            /* 2 x 16KB  (Ch 8K | Cl 8K) */
#define G1_SMEM 114688          /* 112KB -> 2 CTA/SM */

#define G2_STAGE 24576
#define G2_SMEM  (3 * G2_STAGE)

typedef unsigned long long u64;
typedef unsigned int u32;

// ---------------- scratch ------------------------------------------------------
__device__ u32 g_hh[(size_t)B_ * C2 * T_ / 2];          // 32 MB h hi (bf16x2)
__device__ u32 g_hl[(size_t)B_ * C2 * T_ / 2];          // 32 MB h lo
__device__ __nv_bfloat16 g_w1h[C2 * C1], g_w1l[C2 * C1];
__device__ __nv_bfloat16 g_w2h[C3 * C2], g_w2l[C3 * C2];
__device__ float g_b1f[C2], g_b2f[C3];
__device__ float g_ps1[C1 * S1], g_pq1[C1 * S1];
__device__ float g_ps2[C2 * S2], g_pq2[C2 * S2];

// ---------------- helpers ------------------------------------------------------
__device__ __forceinline__ u32 smem_u32(const void* p) {
    u32 a; asm("{ .reg .u64 t; cvta.to.shared.u64 t, %1; cvt.u32.u64 %0, t; }" : "=r"(a) : "l"(p));
    return a;
}
__device__ __forceinline__ void cp16(u32 dst, const void* src) {
    asm volatile("cp.async.cg.shared.global [%0], [%1], 16;" :: "r"(dst), "l"(src));
}
__device__ __forceinline__ void cpcommit() { asm volatile("cp.async.commit_group;" ::: "memory"); }
__device__ __forceinline__ void ldsm4(u32* r, u32 addr) {
    asm volatile("ldmatrix.sync.aligned.m8n8.x4.shared.b16 {%0,%1,%2,%3}, [%4];"
        : "=r"(r[0]), "=r"(r[1]), "=r"(r[2]), "=r"(r[3]) : "r"(addr));
}
__device__ __forceinline__ void ldsm4t(u32* r, u32 addr) {
    asm volatile("ldmatrix.sync.aligned.m8n8.x4.trans.shared.b16 {%0,%1,%2,%3}, [%4];"
        : "=r"(r[0]), "=r"(r[1]), "=r"(r[2]), "=r"(r[3]) : "r"(addr));
}
__device__ __forceinline__ void mma16816(float* d, const u32* a, const u32* b) {
    asm volatile("mma.sync.aligned.m16n8k16.row.col.f32.bf16.bf16.f32 "
        "{%0,%1,%2,%3}, {%4,%5,%6,%7}, {%8,%9}, {%0,%1,%2,%3};"
        : "+f"(d[0]), "+f"(d[1]), "+f"(d[2]), "+f"(d[3])
        : "r"(a[0]), "r"(a[1]), "r"(a[2]), "r"(a[3]), "r"(b[0]), "r"(b[1]));
}
__device__ __forceinline__ void split2(float v0, float v1, u32& h, u32& l) {
    __nv_bfloat162 hh = __floats2bfloat162_rn(v0, v1);
    float r0 = v0 - __bfloat162float(hh.x);
    float r1 = v1 - __bfloat162float(hh.y);
    __nv_bfloat162 ll = __floats2bfloat162_rn(r0, r1);
    h = *(u32*)&hh; l = *(u32*)&ll;
}
__device__ __forceinline__ float4 lds128(u32 addr) {
    float4 v;
    asm volatile("ld.shared.v4.f32 {%0,%1,%2,%3}, [%4];"
        : "=f"(v.x), "=f"(v.y), "=f"(v.z), "=f"(v.w) : "r"(addr));
    return v;
}
__device__ __forceinline__ void sts64(u32 addr, u32 a, u32 b) {
    asm volatile("st.shared.v2.u32 [%0], {%1,%2};" :: "r"(addr), "r"(a), "r"(b));
}

// ---------------- stats1 (pure reduction, no split) -------------------------------
__global__ __launch_bounds__(256) void stats1_kernel(const float* __restrict__ x) {
    __shared__ float sh_s[256], sh_q[256];
    const int c = blockIdx.x, sp = blockIdx.y, tid = threadIdx.x;
    float s = 0.f, q = 0.f;
    #pragma unroll
    for (int j = 0; j < 4; j++) {
        const int b = sp * 4 + j;
        const float4* row = (const float4*)(x + ((size_t)b * C1 + c) * T_);
        float4 a0 = row[tid], a1 = row[tid + 256];
        s += a0.x + a0.y + a0.z + a0.w + a1.x + a1.y + a1.z + a1.w;
        q += a0.x*a0.x + a0.y*a0.y + a0.z*a0.z + a0.w*a0.w
           + a1.x*a1.x + a1.y*a1.y + a1.z*a1.z + a1.w*a1.w;
    }
    sh_s[tid] = s; sh_q[tid] = q;
    __syncthreads();
    for (int off = 128; off > 0; off >>= 1) {
        if (tid < off) { sh_s[tid] += sh_s[tid + off]; sh_q[tid] += sh_q[tid + off]; }
        __syncthreads();
    }
    if (tid == 0) { g_ps1[c * S1 + sp] = sh_s[0]; g_pq1[c * S1 + sp] = sh_q[0]; }
}

// ---------------- stats2 on hh/hl ---------------------------------------------------
__global__ __launch_bounds__(256) void stats2_part_kernel() {
    __shared__ float sh_s[256], sh_q[256];
    const int c = blockIdx.x, sp = blockIdx.y, tid = threadIdx.x;
    uint4 H[4], L[4];
    #pragma unroll
    for (int j = 0; j < 4; j++) {
        int b = sp * 4 + j;
        size_t rowq = ((size_t)b * C2 + c) * T_ / 8;
        H[j] = ((const uint4*)g_hh)[rowq + tid];
        L[j] = ((const uint4*)g_hl)[rowq + tid];
    }
    float s = 0.f, q = 0.f;
    #pragma unroll
    for (int j = 0; j < 4; j++) {
        u32 hw[4] = {H[j].x, H[j].y, H[j].z, H[j].w};
        u32 lw[4] = {L[j].x, L[j].y, L[j].z, L[j].w};
        #pragma unroll
        for (int k = 0; k < 4; k++) {
            __nv_bfloat162 hb = *(__nv_bfloat162*)&hw[k];
            __nv_bfloat162 lb = *(__nv_bfloat162*)&lw[k];
            float v0 = __bfloat162float(hb.x) + __bfloat162float(lb.x);
            float v1 = __bfloat162float(hb.y) + __bfloat162float(lb.y);
            s += v0 + v1;
            q += v0 * v0 + v1 * v1;
        }
    }
    sh_s[tid] = s; sh_q[tid] = q;
    __syncthreads();
    for (int off = 128; off > 0; off >>= 1) {
        if (tid < off) { sh_s[tid] += sh_s[tid + off]; sh_q[tid] += sh_q[tid + off]; }
        __syncthreads();
    }
    if (tid == 0) { g_ps2[c * S2 + sp] = sh_s[0]; g_pq2[c * S2 + sp] = sh_q[0]; }
}

// ---------------- fold1 (finalize fused) --------------------------------------------
__global__ __launch_bounds__(256) void fold1_kernel(const float* __restrict__ w,
                                                    const float* __restrict__ bias,
                                                    const float* __restrict__ bg,
                                                    const float* __restrict__ bb) {
    __shared__ float sa[C1], sd[C1];
    __shared__ float sh[256];
    const int o = blockIdx.x, tid = threadIdx.x;
    const float inv_n = 1.f / (float)(B_ * T_);
    #pragma unroll
    for (int k = tid; k < C1; k += 256) {
        float s = 0.f, q = 0.f;
        #pragma unroll
        for (int i = 0; i < S1; i++) { s += g_ps1[k * S1 + i]; q += g_pq1[k * S1 + i]; }
        float mean = s * inv_n;
        float var  = q * inv_n - mean * mean;
        float av = bg[k] * rsqrtf(var + EPSV);
        sa[k] = av;
        sd[k] = bb[k] - mean * av;
    }
    __syncthreads();
    float acc = 0.f;
    for (int k = tid; k < C1; k += 256) {
        float wv = w[(size_t)o * C1 + k];
        float wf = wv * sa[k];
        __nv_bfloat16 h = __float2bfloat16(wf);
        g_w1h[(size_t)o * C1 + k] = h;
        g_w1l[(size_t)o * C1 + k] = __float2bfloat16(wf - __bfloat162float(h));
        acc += wv * sd[k];
    }
    sh[tid] = acc;
    __syncthreads();
    for (int off = 128; off > 0; off >>= 1) {
        if (tid < off) sh[tid] += sh[tid + off];
        __syncthreads();
    }
    if (tid == 0) g_b1f[o] = bias[o] + sh[0];
}

// ---------------- fold2 (finalize fused) --------------------------------------------
__global__ __launch_bounds__(256) void fold2_kernel(const float* __restrict__ w,
                                                    const float* __restrict__ bias,
                                                    const float* __restrict__ bg,
                                                    const float* __restrict__ bb) {
    __shared__ float sa[C2], sd[C2];
    __shared__ float sh[256];
    const int o = blockIdx.x, tid = threadIdx.x;
    const float inv_n = 1.f / (float)(B_ * T_);
    if (tid < C2) {
        float s = 0.f, q = 0.f;
        #pragma unroll
        for (int i = 0; i < S2; i++) { s += g_ps2[tid * S2 + i]; q += g_pq2[tid * S2 + i]; }
        float mean = s * inv_n;
        float var  = q * inv_n - mean * mean;
        float av = bg[tid] * rsqrtf(var + EPSV);
        sa[tid] = av;
        sd[tid] = bb[tid] - mean * av;
    }
    __syncthreads();
    float acc = 0.f;
    for (int k = tid; k < C2; k += 256) {
        float wv = w[(size_t)o * C2 + k];
        float wf = wv * sa[k];
        __nv_bfloat16 h = __float2bfloat16(wf);
        g_w2h[(size_t)o * C2 + k] = h;
        g_w2l[(size_t)o * C2 + k] = __float2bfloat16(wf - __bfloat162float(h));
        acc += wv * sd[k];
    }
    sh[tid] = acc;
    __syncthreads();
    for (int off = 128; off > 0; off >>= 1) {
        if (tid < off) sh[tid] += sh[tid + off];
        __syncthreads();
    }
    if (tid == 0) g_b2f[o] = bias[o] + sh[0];
}

// ---------------- GEMM1: BM128xBN128, fp32 X in-kernel split, single sync ----------
extern __shared__ char g1s[];

// issue chunk `it`: W hi/lo into W-ring slot it%3, fp32 X into Xf-ring slot it&1
__device__ __forceinline__ void g1_issue(u32 sb0, int it, int m0, int n0, int b,
                                         const float* __restrict__ x, int tid) {
    const int k0 = it * BK;
    const u32 wb = sb0 + O_W + (it - (it / 3) * 3) * 16384;
    #pragma unroll
    for (int j = 0; j < 2; j++) {           // W: 512 chunks each of h/l
        int u = tid + j * 256;
        int row = u >> 2, c = u & 3;
        u32 dst = wb + row * 64 + ((c ^ ((row >> 1) & 3)) << 4);
        size_t src = (size_t)(m0 + row) * (C1 / 8) + (k0 >> 3) + c;
        cp16(dst,        (const uint4*)g_w1h + src);
        cp16(dst + 8192, (const uint4*)g_w1l + src);
    }
    const u32 xb = sb0 + O_XF + (it & 1) * 16384;
    #pragma unroll
    for (int j = 0; j < 4; j++) {           // X fp32: 32 rows x 512B = 1024 chunks
        int u = tid + j * 256;
        int row = u >> 5, c = u & 31;
        u32 dst = xb + row * 512 + c * 16;
        const float* src = x + ((size_t)(b * C1 + k0 + row)) * T_ + n0 + c * 4;
        cp16(dst, src);
    }
    cpcommit();
}

// convert chunk `it`: fp32 Xf slot -> bf16 hi/lo Xc slot (ldsm-B layout, 256B rows)
__device__ __forceinline__ void g1_convert(u32 sb0, int it, int tid) {
    const u32 xf = sb0 + O_XF + (it & 1) * 16384;
    const u32 xc = sb0 + O_XC + (it & 1) * 16384;
    const int k = tid >> 3;
    #pragma unroll
    for (int j = 0; j < 4; j++) {
        int c = (tid & 7) + j * 8;              // fp32 16B chunk index (0..31)
        float4 v = lds128(xf + k * 512 + c * 16);
        u32 h0, l0, h1, l1;
        split2(v.x, v.y, h0, l0);
        split2(v.z, v.w, h1, l1);
        u32 dst = xc + k * 256 + ((((c >> 1) ^ (k & 7))) << 4) + ((c & 1) << 3);
        sts64(dst,        h0, h1);
        sts64(dst + 8192, l0, l1);
    }
}

__global__ __launch_bounds__(256, 2) void gemm1_kernel(const float* __restrict__ x) {
    const int tid = threadIdx.x, lane = tid & 31, wid = tid >> 5;
    const int b = blockIdx.z, m0 = blockIdx.y * BM, n0 = blockIdx.x * BN;
    const int wm = (wid & 3) * 32, wn = (wid >> 2) * 64;
    const u32 sb0 = smem_u32(g1s);

    float acc[2][8][4];
    #pragma unroll
    for (int mi = 0; mi < 2; mi++)
        #pragma unroll
        for (int nj = 0; nj < 8; nj++)
            #pragma unroll
            for (int r = 0; r < 4; r++) acc[mi][nj][r] = 0.f;

    g1_issue(sb0, 0, m0, n0, b, x, tid);
    g1_issue(sb0, 1, m0, n0, b, x, tid);
    asm volatile("cp.async.wait_group 1;" ::: "memory");
    __syncthreads();
    g1_convert(sb0, 0, tid);

    #pragma unroll 1
    for (int it = 0; it < KIT; it++) {
        asm volatile("cp.async.wait_group 0;" ::: "memory");
        __syncthreads();
        if (it + 2 < KIT) g1_issue(sb0, it + 2, m0, n0, b, x, tid);
        if (it + 1 < KIT) g1_convert(sb0, it + 1, tid);

        const u32 wb = sb0 + O_W + (it - (it / 3) * 3) * 16384;
        const u32 cb = sb0 + O_XC + (it & 1) * 16384;
        #pragma unroll
        for (int ks = 0; ks < 2; ks++) {
            u32 ah[2][4], al[2][4];
            #pragma unroll
            for (int mi = 0; mi < 2; mi++) {
                int ml = wm + mi * 16 + (lane & 15);
                int kk = ks * 16 + (lane >> 4) * 8;
                u32 a_addr = wb + ml * 64 + (((kk >> 3) ^ ((ml >> 1) & 3)) << 4);
                ldsm4(ah[mi], a_addr);
                ldsm4(al[mi], a_addr + 8192);
            }
            const int mat = lane >> 3, rr = lane & 7;
            #pragma unroll
            for (int nb = 0; nb < 4; nb++) {
                int kk = ks * 16 + (mat & 1) * 8 + rr;
                int nn = wn + nb * 16 + (mat >> 1) * 8;
                u32 b_addr = cb + kk * 256 + (((nn >> 3) ^ (kk & 7)) << 4);
                u32 bh[4], bl[4];
                ldsm4t(bh, b_addr);
                ldsm4t(bl, b_addr + 8192);
                #pragma unroll
                for (int mi = 0; mi < 2; mi++) {
                    mma16816(acc[mi][2*nb],     ah[mi], bh);
                    mma16816(acc[mi][2*nb],     ah[mi], bl);
                    mma16816(acc[mi][2*nb],     al[mi], bh);
                    mma16816(acc[mi][2*nb + 1], ah[mi], bh + 2);
                    mma16816(acc[mi][2*nb + 1], ah[mi], bl + 2);
                    mma16816(acc[mi][2*nb + 1], al[mi], bh + 2);
                }
            }
        }
    }

    // epilogue: v = relu(acc + bias); split -> g_hh / g_hl
    const int g = lane >> 2, q = lane & 3;
    #pragma unroll
    for (int mi = 0; mi < 2; mi++) {
        #pragma unroll
        for (int rw = 0; rw < 2; rw++) {
            const int m = m0 + wm + mi * 16 + g + rw * 8;
            const float bias = g_b1f[m];
            size_t rowu = (((size_t)b * C2 + m) * T_ + n0 + wn) / 2;
            #pragma unroll
            for (int nj = 0; nj < 8; nj++) {
                float v0 = fmaxf(acc[mi][nj][rw * 2 + 0] + bias, 0.f);
                float v1 = fmaxf(acc[mi][nj][rw * 2 + 1] + bias, 0.f);
                u32 h, l;
                split2(v0, v1, h, l);
                g_hh[rowu + nj * 4 + q] = h;
                g_hl[rowu + nj * 4 + q] = l;
            }
        }
    }
}

// ---------------- GEMM2: cp.async 3-stage, mma bf16 3-term (R5, proven) ------------
extern __shared__ char g2s[];

__device__ __forceinline__ void g2_issue(u32 sb, int it, int n0, int b, int tid) {
    const int k0 = it * 32;
    {
        int row = tid >> 2, c = tid & 3;
        u32 dst = sb + row * 64 + ((c ^ ((row >> 1) & 3)) << 4);
        size_t src = (size_t)row * (C2 / 8) + (k0 >> 3) + c;
        cp16(dst,        (const uint4*)g_w2h + src);
        cp16(dst + 4096, (const uint4*)g_w2l + src);
    }
    #pragma unroll
    for (int j = 0; j < 2; j++) {
        int u = tid + j * 256;
        int row = u >> 4, c = u & 15;
        u32 dst = sb + 8192 + row * 256 + ((c ^ (row & 7)) << 4);
        size_t src = (((size_t)(b * C2 + k0 + row)) * T_ + n0) / 8 + c;
        cp16(dst,        (const uint4*)g_hh + src);
        cp16(dst + 8192, (const uint4*)g_hl + src);
    }
    cpcommit();
}

__global__ __launch_bounds__(256, 2) void gemm2_kernel(float* __restrict__ out) {
    const int tid = threadIdx.x, lane = tid & 31, wid = tid >> 5;
    const int b = blockIdx.z, n0 = blockIdx.x * 128;
    const int wm = (wid & 1) * 32, wn = (wid >> 1) * 32;
    const u32 sb0 = smem_u32(g2s);

    float acc[2][4][4];
    #pragma unroll
    for (int mi = 0; mi < 2; mi++)
        #pragma unroll
        for (int nj = 0; nj < 4; nj++)
            #pragma unroll
            for (int r = 0; r < 4; r++) acc[mi][nj][r] = 0.f;

    g2_issue(sb0,            0, n0, b, tid);
    g2_issue(sb0 + G2_STAGE, 1, n0, b, tid);

    #pragma unroll 1
    for (int it = 0; it < KIT2; it++) {
        if (it < KIT2 - 1) asm volatile("cp.async.wait_group 1;" ::: "memory");
        else               asm volatile("cp.async.wait_group 0;" ::: "memory");
        __syncthreads();
        if (it + 2 < KIT2) {
            int sl = it + 2 - ((it + 2) / 3) * 3;
            g2_issue(sb0 + sl * G2_STAGE, it + 2, n0, b, tid);
        }
        const u32 Bbase = sb0 + (it - (it / 3) * 3) * G2_STAGE;
        #pragma unroll
        for (int ks = 0; ks < 2; ks++) {
            u32 ah[2][4], al[2][4];
            #pragma unroll
            for (int mi = 0; mi < 2; mi++) {
                int ml = wm + mi * 16 + (lane & 15);
                int kk = ks * 16 + (lane >> 4) * 8;
                u32 a_addr = Bbase + ml * 64 + (((kk >> 3) ^ ((ml >> 1) & 3)) << 4);
                ldsm4(ah[mi], a_addr);
                ldsm4(al[mi], a_addr + 4096);
            }
            const int mat = lane >> 3, rr = lane & 7;
            #pragma unroll
            for (int nbk = 0; nbk < 2; nbk++) {
                int kk = ks * 16 + (mat & 1) * 8 + rr;
                int nn = wn + nbk * 16 + (mat >> 1) * 8;
                u32 b_addr = Bbase + 8192 + kk * 256 + (((nn >> 3) ^ (kk & 7)) << 4);
                u32 bh[4], bl[4];
                ldsm4t(bh, b_addr);
                ldsm4t(bl, b_addr + 8192);
                #pragma unroll
                for (int mi = 0; mi < 2; mi++) {
                    mma16816(acc[mi][2*nbk],     ah[mi], bh);
                    mma16816(acc[mi][2*nbk],     ah[mi], bl);
                    mma16816(acc[mi][2*nbk],     al[mi], bh);
                    mma16816(acc[mi][2*nbk + 1], ah[mi], bh + 2);
                    mma16816(acc[mi][2*nbk + 1], ah[mi], bl + 2);
                    mma16816(acc[mi][2*nbk + 1], al[mi], bh + 2);
                }
            }
        }
    }

    const int g = lane >> 2, q = lane & 3;
    #pragma unroll
    for (int mi = 0; mi < 2; mi++) {
        #pragma unroll
        for (int rw = 0; rw < 2; rw++) {
            const int o = wm + mi * 16 + g + rw * 8;
            const float bias = g_b2f[o];
            const size_t base = (o < 32)
                ? ((size_t)b * 32 * T_ + (size_t)o * T_)
                : (MUHALF + (size_t)b * 32 * T_ + (size_t)(o - 32) * T_);
            #pragma unroll
            for (int nj = 0; nj < 4; nj++) {
                float2 v;
                v.x = acc[mi][nj][rw * 2 + 0] + bias;
                v.y = acc[mi][nj][rw * 2 + 1] + bias;
                *(float2*)(out + base + n0 + wn + nj * 8 + q * 2) = v;
            }
        }
    }
}

// ---------------- launcher -----------------------------------------------------------
extern "C" void kernel_launch(void* const* d_in, const int* in_sizes, int n_in,
                              void* d_out, int out_size) {
    const float* x     = (const float*)d_in[0];
    const float* bn1_g = (const float*)d_in[1];
    const float* bn1_b = (const float*)d_in[2];
    const float* w1    = (const float*)d_in[3];
    const float* b1    = (const float*)d_in[4];
    const float* bn2_g = (const float*)d_in[5];
    const float* bn2_b = (const float*)d_in[6];
    const float* w2    = (const float*)d_in[7];
    const float* b2    = (const float*)d_in[8];
    float* out = (float*)d_out;

    cudaFuncSetAttribute(gemm1_kernel, cudaFuncAttributeMaxDynamicSharedMemorySize, G1_SMEM);
    cudaFuncSetAttribute(gemm2_kernel, cudaFuncAttributeMaxDynamicSharedMemorySize, G2_SMEM);

    stats1_kernel<<<dim3(C1, S1), 256>>>(x);
    fold1_kernel<<<C2, 256>>>(w1, b1, bn1_g, bn1_b);
    gemm1_kernel<<<dim3(T_ / BN, C2 / BM, B_), 256, G1_SMEM>>>(x);
    stats2_part_kernel<<<dim3(C2, S2), 256>>>();
    fold2_kernel<<<C3, 256>>>(w2, b2, bn2_g, bn2_b);
    gemm2_kernel<<<dim3(T_ / 128, 1, B_), 256, G2_SMEM>>>(out);
}

// round 10
// speedup vs baseline: 1.3009x; 1.0399x over previous
#include <cuda_runtime.h>
#include <cuda_bf16.h>

#define B_   32
#define C1   1024
#define C2   256
#define C3   64
#define T_   2048
#define EPSV 1e-5f
#define MUHALF ((size_t)B_ * 32 * T_)
#define S1   8

#define BM 128
#define BN 128
#define BK 32
#define KIT  (C1 / BK)          /* 32 */
#define KIT2 (C2 / BK)          /* 8  */
#define G1_STAGE 32768
#define G1_SMEM  (3 * G1_STAGE) /* 96KB, 3-stage ring */
#define G2_STAGE 24576
#define G2_SMEM  (3 * G2_STAGE) /* 72KB, 3-stage ring */

typedef unsigned long long u64;
typedef unsigned int u32;

// ---------------- scratch (__device__ globals: allocation-free) --------------
__device__ __nv_bfloat16 g_xh[(size_t)B_ * C1 * T_];   // 128 MB  X hi
__device__ __nv_bfloat16 g_xl[(size_t)B_ * C1 * T_];   // 128 MB  X lo
__device__ u32 g_hh[(size_t)B_ * C2 * T_ / 2];          // 32 MB   h hi (bf16x2)
__device__ u32 g_hl[(size_t)B_ * C2 * T_ / 2];          // 32 MB   h lo
__device__ __nv_bfloat16 g_w1h[C2 * C1], g_w1l[C2 * C1];
__device__ __nv_bfloat16 g_w2h[C3 * C2], g_w2l[C3 * C2];
__device__ float g_b1f[C2], g_b2f[C3];
__device__ float g_ps1[C1 * S1], g_pq1[C1 * S1];
__device__ float g_s2[C2 * B_], g_q2[C2 * B_];          // h stats, b-bucketed

// ---------------- helpers ------------------------------------------------------
__device__ __forceinline__ u32 smem_u32(const void* p) {
    u32 a; asm("{ .reg .u64 t; cvta.to.shared.u64 t, %1; cvt.u32.u64 %0, t; }" : "=r"(a) : "l"(p));
    return a;
}
__device__ __forceinline__ void cp16(u32 dst, const void* src) {
    asm volatile("cp.async.cg.shared.global [%0], [%1], 16;" :: "r"(dst), "l"(src));
}
__device__ __forceinline__ void cpcommit() { asm volatile("cp.async.commit_group;" ::: "memory"); }
__device__ __forceinline__ void ldsm4(u32* r, u32 addr) {
    asm volatile("ldmatrix.sync.aligned.m8n8.x4.shared.b16 {%0,%1,%2,%3}, [%4];"
        : "=r"(r[0]), "=r"(r[1]), "=r"(r[2]), "=r"(r[3]) : "r"(addr));
}
__device__ __forceinline__ void ldsm4t(u32* r, u32 addr) {
    asm volatile("ldmatrix.sync.aligned.m8n8.x4.trans.shared.b16 {%0,%1,%2,%3}, [%4];"
        : "=r"(r[0]), "=r"(r[1]), "=r"(r[2]), "=r"(r[3]) : "r"(addr));
}
__device__ __forceinline__ void mma16816(float* d, const u32* a, const u32* b) {
    asm volatile("mma.sync.aligned.m16n8k16.row.col.f32.bf16.bf16.f32 "
        "{%0,%1,%2,%3}, {%4,%5,%6,%7}, {%8,%9}, {%0,%1,%2,%3};"
        : "+f"(d[0]), "+f"(d[1]), "+f"(d[2]), "+f"(d[3])
        : "r"(a[0]), "r"(a[1]), "r"(a[2]), "r"(a[3]), "r"(b[0]), "r"(b[1]));
}
__device__ __forceinline__ void split2(float v0, float v1, u32& h, u32& l) {
    __nv_bfloat162 hh = __floats2bfloat162_rn(v0, v1);
    float r0 = v0 - __bfloat162float(hh.x);
    float r1 = v1 - __bfloat162float(hh.y);
    __nv_bfloat162 ll = __floats2bfloat162_rn(r0, r1);
    h = *(u32*)&hh; l = *(u32*)&ll;
}

// ---------------- stats1 fused with X hi/lo split (16B stores) -------------------
__global__ __launch_bounds__(256) void stats1_split_kernel(const float* __restrict__ x) {
    __shared__ float sh_s[256], sh_q[256];
    const int c = blockIdx.x, sp = blockIdx.y, tid = threadIdx.x;
    float s = 0.f, q = 0.f;
    #pragma unroll
    for (int j = 0; j < 4; j++) {
        const int b = sp * 4 + j;
        const size_t base = ((size_t)b * C1 + c) * T_;
        float4 a0 = ((const float4*)(x + base))[tid * 2];
        float4 a1 = ((const float4*)(x + base))[tid * 2 + 1];
        s += a0.x + a0.y + a0.z + a0.w + a1.x + a1.y + a1.z + a1.w;
        q += a0.x*a0.x + a0.y*a0.y + a0.z*a0.z + a0.w*a0.w
           + a1.x*a1.x + a1.y*a1.y + a1.z*a1.z + a1.w*a1.w;
        u32 h[4], l[4];
        split2(a0.x, a0.y, h[0], l[0]); split2(a0.z, a0.w, h[1], l[1]);
        split2(a1.x, a1.y, h[2], l[2]); split2(a1.z, a1.w, h[3], l[3]);
        ((uint4*)(g_xh + base))[tid] = make_uint4(h[0], h[1], h[2], h[3]);
        ((uint4*)(g_xl + base))[tid] = make_uint4(l[0], l[1], l[2], l[3]);
    }
    sh_s[tid] = s; sh_q[tid] = q;
    __syncthreads();
    for (int off = 128; off > 0; off >>= 1) {
        if (tid < off) { sh_s[tid] += sh_s[tid + off]; sh_q[tid] += sh_q[tid + off]; }
        __syncthreads();
    }
    if (tid == 0) { g_ps1[c * S1 + sp] = sh_s[0]; g_pq1[c * S1 + sp] = sh_q[0]; }
}

// ---------------- fold1 (finalize fused; also zeroes h-stat buckets) --------------
__global__ __launch_bounds__(256) void fold1_kernel(const float* __restrict__ w,
                                                    const float* __restrict__ bias,
                                                    const float* __restrict__ bg,
                                                    const float* __restrict__ bb) {
    __shared__ float sa[C1], sd[C1];
    __shared__ float sh[256];
    const int o = blockIdx.x, tid = threadIdx.x;
    if (blockIdx.x < (C2 * B_) / 256) {
        int idx = blockIdx.x * 256 + tid;
        g_s2[idx] = 0.f;
        g_q2[idx] = 0.f;
    }
    const float inv_n = 1.f / (float)(B_ * T_);
    #pragma unroll
    for (int k = tid; k < C1; k += 256) {
        float s = 0.f, q = 0.f;
        #pragma unroll
        for (int i = 0; i < S1; i++) { s += g_ps1[k * S1 + i]; q += g_pq1[k * S1 + i]; }
        float mean = s * inv_n;
        float var  = q * inv_n - mean * mean;
        float av = bg[k] * rsqrtf(var + EPSV);
        sa[k] = av;
        sd[k] = bb[k] - mean * av;
    }
    __syncthreads();
    float acc = 0.f;
    for (int k = tid; k < C1; k += 256) {
        float wv = w[(size_t)o * C1 + k];
        float wf = wv * sa[k];
        __nv_bfloat16 h = __float2bfloat16(wf);
        g_w1h[(size_t)o * C1 + k] = h;
        g_w1l[(size_t)o * C1 + k] = __float2bfloat16(wf - __bfloat162float(h));
        acc += wv * sd[k];
    }
    sh[tid] = acc;
    __syncthreads();
    for (int off = 128; off > 0; off >>= 1) {
        if (tid < off) sh[tid] += sh[tid + off];
        __syncthreads();
    }
    if (tid == 0) g_b1f[o] = bias[o] + sh[0];
}

// ---------------- fold2 (reads b-bucketed h stats) ----------------------------------
__global__ __launch_bounds__(256) void fold2_kernel(const float* __restrict__ w,
                                                    const float* __restrict__ bias,
                                                    const float* __restrict__ bg,
                                                    const float* __restrict__ bb) {
    __shared__ float sa[C2], sd[C2];
    __shared__ float sh[256];
    const int o = blockIdx.x, tid = threadIdx.x;
    const float inv_n = 1.f / (float)(B_ * T_);
    {
        float s = 0.f, q = 0.f;
        #pragma unroll
        for (int i = 0; i < B_; i++) { s += g_s2[tid * B_ + i]; q += g_q2[tid * B_ + i]; }
        float mean = s * inv_n;
        float var  = q * inv_n - mean * mean;
        float av = bg[tid] * rsqrtf(var + EPSV);
        sa[tid] = av;
        sd[tid] = bb[tid] - mean * av;
    }
    __syncthreads();
    float acc = 0.f;
    for (int k = tid; k < C2; k += 256) {
        float wv = w[(size_t)o * C2 + k];
        float wf = wv * sa[k];
        __nv_bfloat16 h = __float2bfloat16(wf);
        g_w2h[(size_t)o * C2 + k] = h;
        g_w2l[(size_t)o * C2 + k] = __float2bfloat16(wf - __bfloat162float(h));
        acc += wv * sd[k];
    }
    sh[tid] = acc;
    __syncthreads();
    for (int off = 128; off > 0; off >>= 1) {
        if (tid < off) sh[tid] += sh[tid + off];
        __syncthreads();
    }
    if (tid == 0) g_b2f[o] = bias[o] + sh[0];
}

// ---------------- GEMM1: cp.async 3-stage single-sync, mma bf16 3-term -------------
// Stage layout (32KB): Ah[0,8K) Al[8K,16K) Bh[16K,24K) Bl[24K,32K)
extern __shared__ char g1s[];

__device__ __forceinline__ void g1_issue(u32 sb, int it, int m0, int n0, int b, int tid) {
    const int k0 = it * BK;
    #pragma unroll
    for (int j = 0; j < 2; j++) {           // A: 512 uint4 each h/l
        int u = tid + j * 256;
        int row = u >> 2, c = u & 3;
        u32 dst = sb + row * 64 + ((c ^ ((row >> 1) & 3)) << 4);
        size_t src = (size_t)(m0 + row) * (C1 / 8) + (k0 >> 3) + c;
        cp16(dst,        (const uint4*)g_w1h + src);
        cp16(dst + 8192, (const uint4*)g_w1l + src);
    }
    #pragma unroll
    for (int j = 0; j < 2; j++) {           // B: 512 uint4 each h/l
        int u = tid + j * 256;
        int row = u >> 4, c = u & 15;
        u32 dst = sb + 16384 + row * 256 + ((c ^ (row & 7)) << 4);
        size_t src = (((size_t)(b * C1 + k0 + row)) * T_ + n0) / 8 + c;
        cp16(dst,        (const uint4*)g_xh + src);
        cp16(dst + 8192, (const uint4*)g_xl + src);
    }
    cpcommit();
}

__global__ __launch_bounds__(256, 2) void gemm1_kernel() {
    const int tid = threadIdx.x, lane = tid & 31, wid = tid >> 5;
    const int b = blockIdx.z, m0 = blockIdx.y * BM, n0 = blockIdx.x * BN;
    const int wm = (wid & 3) * 32, wn = (wid >> 2) * 64;
    const u32 sb0 = smem_u32(g1s);

    float acc[2][8][4];
    #pragma unroll
    for (int mi = 0; mi < 2; mi++)
        #pragma unroll
        for (int nj = 0; nj < 8; nj++)
            #pragma unroll
            for (int r = 0; r < 4; r++) acc[mi][nj][r] = 0.f;

    g1_issue(sb0,            0, m0, n0, b, tid);
    g1_issue(sb0 + G1_STAGE, 1, m0, n0, b, tid);

    #pragma unroll 1
    for (int it = 0; it < KIT; it++) {
        if (it < KIT - 1) asm volatile("cp.async.wait_group 1;" ::: "memory");
        else              asm volatile("cp.async.wait_group 0;" ::: "memory");
        __syncthreads();
        if (it + 2 < KIT) {
            int sl = it + 2 - ((it + 2) / 3) * 3;
            g1_issue(sb0 + sl * G1_STAGE, it + 2, m0, n0, b, tid);
        }
        const u32 Abase = sb0 + (it - (it / 3) * 3) * G1_STAGE;
        #pragma unroll
        for (int ks = 0; ks < 2; ks++) {
            u32 ah[2][4], al[2][4];
            #pragma unroll
            for (int mi = 0; mi < 2; mi++) {
                int ml = wm + mi * 16 + (lane & 15);
                int kk = ks * 16 + (lane >> 4) * 8;
                u32 a_addr = Abase + ml * 64 + (((kk >> 3) ^ ((ml >> 1) & 3)) << 4);
                ldsm4(ah[mi], a_addr);
                ldsm4(al[mi], a_addr + 8192);
            }
            const int mat = lane >> 3, rr = lane & 7;
            #pragma unroll
            for (int nb = 0; nb < 4; nb++) {
                int kk = ks * 16 + (mat & 1) * 8 + rr;
                int nn = wn + nb * 16 + (mat >> 1) * 8;
                u32 b_addr = Abase + 16384 + kk * 256 + (((nn >> 3) ^ (kk & 7)) << 4);
                u32 bh[4], bl[4];
                ldsm4t(bh, b_addr);
                ldsm4t(bl, b_addr + 8192);
                #pragma unroll
                for (int mi = 0; mi < 2; mi++) {
                    mma16816(acc[mi][2*nb],     ah[mi], bh);
                    mma16816(acc[mi][2*nb],     ah[mi], bl);
                    mma16816(acc[mi][2*nb],     al[mi], bh);
                    mma16816(acc[mi][2*nb + 1], ah[mi], bh + 2);
                    mma16816(acc[mi][2*nb + 1], ah[mi], bl + 2);
                    mma16816(acc[mi][2*nb + 1], al[mi], bh + 2);
                }
            }
        }
    }

    // epilogue: v = relu(acc + bias); split -> g_hh/g_hl; fused h-stats (s,q)
    const int g = lane >> 2, q = lane & 3;
    #pragma unroll
    for (int mi = 0; mi < 2; mi++) {
        #pragma unroll
        for (int rw = 0; rw < 2; rw++) {
            const int m = m0 + wm + mi * 16 + g + rw * 8;
            const float bias = g_b1f[m];
            size_t rowu = (((size_t)b * C2 + m) * T_ + n0 + wn) / 2;
            float s = 0.f, qs = 0.f;
            #pragma unroll
            for (int nj = 0; nj < 8; nj++) {
                float v0 = fmaxf(acc[mi][nj][rw * 2 + 0] + bias, 0.f);
                float v1 = fmaxf(acc[mi][nj][rw * 2 + 1] + bias, 0.f);
                s  += v0 + v1;
                qs += v0 * v0 + v1 * v1;
                u32 h, l;
                split2(v0, v1, h, l);
                g_hh[rowu + nj * 4 + q] = h;
                g_hl[rowu + nj * 4 + q] = l;
            }
            // reduce (s,qs) across the 4 lanes (q=0..3) owning this row
            s  += __shfl_down_sync(0xffffffffu, s, 2);
            s  += __shfl_down_sync(0xffffffffu, s, 1);
            qs += __shfl_down_sync(0xffffffffu, qs, 2);
            qs += __shfl_down_sync(0xffffffffu, qs, 1);
            if (q == 0) {
                atomicAdd(&g_s2[m * B_ + b], s);
                atomicAdd(&g_q2[m * B_ + b], qs);
            }
        }
    }
}

// ---------------- GEMM2: cp.async 3-stage single-sync, mma bf16 3-term -------------
extern __shared__ char g2s[];

__device__ __forceinline__ void g2_issue(u32 sb, int it, int n0, int b, int tid) {
    const int k0 = it * 32;
    {
        int row = tid >> 2, c = tid & 3;
        u32 dst = sb + row * 64 + ((c ^ ((row >> 1) & 3)) << 4);
        size_t src = (size_t)row * (C2 / 8) + (k0 >> 3) + c;
        cp16(dst,        (const uint4*)g_w2h + src);
        cp16(dst + 4096, (const uint4*)g_w2l + src);
    }
    #pragma unroll
    for (int j = 0; j < 2; j++) {
        int u = tid + j * 256;
        int row = u >> 4, c = u & 15;
        u32 dst = sb + 8192 + row * 256 + ((c ^ (row & 7)) << 4);
        size_t src = (((size_t)(b * C2 + k0 + row)) * T_ + n0) / 8 + c;
        cp16(dst,        (const uint4*)g_hh + src);
        cp16(dst + 8192, (const uint4*)g_hl + src);
    }
    cpcommit();
}

__global__ __launch_bounds__(256, 2) void gemm2_kernel(float* __restrict__ out) {
    const int tid = threadIdx.x, lane = tid & 31, wid = tid >> 5;
    const int b = blockIdx.z, n0 = blockIdx.x * 128;
    const int wm = (wid & 1) * 32, wn = (wid >> 1) * 32;
    const u32 sb0 = smem_u32(g2s);

    float acc[2][4][4];
    #pragma unroll
    for (int mi = 0; mi < 2; mi++)
        #pragma unroll
        for (int nj = 0; nj < 4; nj++)
            #pragma unroll
            for (int r = 0; r < 4; r++) acc[mi][nj][r] = 0.f;

    g2_issue(sb0,            0, n0, b, tid);
    g2_issue(sb0 + G2_STAGE, 1, n0, b, tid);

    #pragma unroll 1
    for (int it = 0; it < KIT2; it++) {
        if (it < KIT2 - 1) asm volatile("cp.async.wait_group 1;" ::: "memory");
        else               asm volatile("cp.async.wait_group 0;" ::: "memory");
        __syncthreads();
        if (it + 2 < KIT2) {
            int sl = it + 2 - ((it + 2) / 3) * 3;
            g2_issue(sb0 + sl * G2_STAGE, it + 2, n0, b, tid);
        }
        const u32 Bbase = sb0 + (it - (it / 3) * 3) * G2_STAGE;
        #pragma unroll
        for (int ks = 0; ks < 2; ks++) {
            u32 ah[2][4], al[2][4];
            #pragma unroll
            for (int mi = 0; mi < 2; mi++) {
                int ml = wm + mi * 16 + (lane & 15);
                int kk = ks * 16 + (lane >> 4) * 8;
                u32 a_addr = Bbase + ml * 64 + (((kk >> 3) ^ ((ml >> 1) & 3)) << 4);
                ldsm4(ah[mi], a_addr);
                ldsm4(al[mi], a_addr + 4096);
            }
            const int mat = lane >> 3, rr = lane & 7;
            #pragma unroll
            for (int nbk = 0; nbk < 2; nbk++) {
                int kk = ks * 16 + (mat & 1) * 8 + rr;
                int nn = wn + nbk * 16 + (mat >> 1) * 8;
                u32 b_addr = Bbase + 8192 + kk * 256 + (((nn >> 3) ^ (kk & 7)) << 4);
                u32 bh[4], bl[4];
                ldsm4t(bh, b_addr);
                ldsm4t(bl, b_addr + 8192);
                #pragma unroll
                for (int mi = 0; mi < 2; mi++) {
                    mma16816(acc[mi][2*nbk],     ah[mi], bh);
                    mma16816(acc[mi][2*nbk],     ah[mi], bl);
                    mma16816(acc[mi][2*nbk],     al[mi], bh);
                    mma16816(acc[mi][2*nbk + 1], ah[mi], bh + 2);
                    mma16816(acc[mi][2*nbk + 1], ah[mi], bl + 2);
                    mma16816(acc[mi][2*nbk + 1], al[mi], bh + 2);
                }
            }
        }
    }

    const int g = lane >> 2, q = lane & 3;
    #pragma unroll
    for (int mi = 0; mi < 2; mi++) {
        #pragma unroll
        for (int rw = 0; rw < 2; rw++) {
            const int o = wm + mi * 16 + g + rw * 8;
            const float bias = g_b2f[o];
            const size_t base = (o < 32)
                ? ((size_t)b * 32 * T_ + (size_t)o * T_)
                : (MUHALF + (size_t)b * 32 * T_ + (size_t)(o - 32) * T_);
            #pragma unroll
            for (int nj = 0; nj < 4; nj++) {
                float2 v;
                v.x = acc[mi][nj][rw * 2 + 0] + bias;
                v.y = acc[mi][nj][rw * 2 + 1] + bias;
                *(float2*)(out + base + n0 + wn + nj * 8 + q * 2) = v;
            }
        }
    }
}

// ---------------- launcher -----------------------------------------------------------
extern "C" void kernel_launch(void* const* d_in, const int* in_sizes, int n_in,
                              void* d_out, int out_size) {
    const float* x     = (const float*)d_in[0];
    const float* bn1_g = (const float*)d_in[1];
    const float* bn1_b = (const float*)d_in[2];
    const float* w1    = (const float*)d_in[3];
    const float* b1    = (const float*)d_in[4];
    const float* bn2_g = (const float*)d_in[5];
    const float* bn2_b = (const float*)d_in[6];
    const float* w2    = (const float*)d_in[7];
    const float* b2    = (const float*)d_in[8];
    float* out = (float*)d_out;

    cudaFuncSetAttribute(gemm1_kernel, cudaFuncAttributeMaxDynamicSharedMemorySize, G1_SMEM);
    cudaFuncSetAttribute(gemm2_kernel, cudaFuncAttributeMaxDynamicSharedMemorySize, G2_SMEM);

    stats1_split_kernel<<<dim3(C1, S1), 256>>>(x);
    fold1_kernel<<<C2, 256>>>(w1, b1, bn1_g, bn1_b);
    gemm1_kernel<<<dim3(T_ / BN, C2 / BM, B_), 256, G1_SMEM>>>();
    fold2_kernel<<<C3, 256>>>(w2, b2, bn2_g, bn2_b);
    gemm2_kernel<<<dim3(T_ / 128, 1, B_), 256, G2_SMEM>>>(out);
}

// round 11
// speedup vs baseline: 1.3024x; 1.0012x over previous
#include <cuda_runtime.h>
#include <cuda_bf16.h>

#define B_   32
#define C1   1024
#define C2   256
#define C3   64
#define T_   2048
#define EPSV 1e-5f
#define MUHALF ((size_t)B_ * 32 * T_)
#define S1   8

#define BM 128
#define BN 128
#define BK 32
#define KIT  (C1 / BK)          /* 32 */
#define KIT2 (C2 / BK)          /* 8  */
#define G1_STAGE 32768
#define G1_SMEM  (3 * G1_STAGE) /* 96KB, 3-stage ring */
#define G2_STAGE 24576
#define G2_SMEM  (3 * G2_STAGE) /* 72KB, 3-stage ring */

typedef unsigned long long u64;
typedef unsigned int u32;

// ---------------- scratch (__device__ globals: allocation-free) --------------
__device__ __nv_bfloat16 g_xh[(size_t)B_ * C1 * T_];   // 128 MB  X hi
__device__ __nv_bfloat16 g_xl[(size_t)B_ * C1 * T_];   // 128 MB  X lo
__device__ u32 g_hh[(size_t)B_ * C2 * T_ / 2];          // 32 MB   h hi (bf16x2)
__device__ u32 g_hl[(size_t)B_ * C2 * T_ / 2];          // 32 MB   h lo
__device__ __nv_bfloat16 g_w1h[C2 * C1], g_w1l[C2 * C1];
__device__ __nv_bfloat16 g_w2h[C3 * C2], g_w2l[C3 * C2];
__device__ float g_b1f[C2], g_b2f[C3];
__device__ float g_ps1[C1 * S1], g_pq1[C1 * S1];
__device__ float g_s2[C2 * B_], g_q2[C2 * B_];          // h stats, b-bucketed

// ---------------- helpers ------------------------------------------------------
__device__ __forceinline__ u32 smem_u32(const void* p) {
    u32 a; asm("{ .reg .u64 t; cvta.to.shared.u64 t, %1; cvt.u32.u64 %0, t; }" : "=r"(a) : "l"(p));
    return a;
}
__device__ __forceinline__ void cp16(u32 dst, const void* src) {
    asm volatile("cp.async.cg.shared.global [%0], [%1], 16;" :: "r"(dst), "l"(src));
}
__device__ __forceinline__ void cpcommit() { asm volatile("cp.async.commit_group;" ::: "memory"); }
__device__ __forceinline__ void ldsm4(u32* r, u32 addr) {
    asm volatile("ldmatrix.sync.aligned.m8n8.x4.shared.b16 {%0,%1,%2,%3}, [%4];"
        : "=r"(r[0]), "=r"(r[1]), "=r"(r[2]), "=r"(r[3]) : "r"(addr));
}
__device__ __forceinline__ void ldsm4t(u32* r, u32 addr) {
    asm volatile("ldmatrix.sync.aligned.m8n8.x4.trans.shared.b16 {%0,%1,%2,%3}, [%4];"
        : "=r"(r[0]), "=r"(r[1]), "=r"(r[2]), "=r"(r[3]) : "r"(addr));
}
__device__ __forceinline__ void mma16816(float* d, const u32* a, const u32* b) {
    asm volatile("mma.sync.aligned.m16n8k16.row.col.f32.bf16.bf16.f32 "
        "{%0,%1,%2,%3}, {%4,%5,%6,%7}, {%8,%9}, {%0,%1,%2,%3};"
        : "+f"(d[0]), "+f"(d[1]), "+f"(d[2]), "+f"(d[3])
        : "r"(a[0]), "r"(a[1]), "r"(a[2]), "r"(a[3]), "r"(b[0]), "r"(b[1]));
}
__device__ __forceinline__ void split2(float v0, float v1, u32& h, u32& l) {
    __nv_bfloat162 hh = __floats2bfloat162_rn(v0, v1);
    float r0 = v0 - __bfloat162float(hh.x);
    float r1 = v1 - __bfloat162float(hh.y);
    __nv_bfloat162 ll = __floats2bfloat162_rn(r0, r1);
    h = *(u32*)&hh; l = *(u32*)&ll;
}

// ---------------- stats1 fused with X hi/lo split (16B stores) -------------------
__global__ __launch_bounds__(256) void stats1_split_kernel(const float* __restrict__ x) {
    __shared__ float sh_s[256], sh_q[256];
    const int c = blockIdx.x, sp = blockIdx.y, tid = threadIdx.x;
    float s = 0.f, q = 0.f;
    #pragma unroll
    for (int j = 0; j < 4; j++) {
        const int b = sp * 4 + j;
        const size_t base = ((size_t)b * C1 + c) * T_;
        float4 a0 = ((const float4*)(x + base))[tid * 2];
        float4 a1 = ((const float4*)(x + base))[tid * 2 + 1];
        s += a0.x + a0.y + a0.z + a0.w + a1.x + a1.y + a1.z + a1.w;
        q += a0.x*a0.x + a0.y*a0.y + a0.z*a0.z + a0.w*a0.w
           + a1.x*a1.x + a1.y*a1.y + a1.z*a1.z + a1.w*a1.w;
        u32 h[4], l[4];
        split2(a0.x, a0.y, h[0], l[0]); split2(a0.z, a0.w, h[1], l[1]);
        split2(a1.x, a1.y, h[2], l[2]); split2(a1.z, a1.w, h[3], l[3]);
        ((uint4*)(g_xh + base))[tid] = make_uint4(h[0], h[1], h[2], h[3]);
        ((uint4*)(g_xl + base))[tid] = make_uint4(l[0], l[1], l[2], l[3]);
    }
    sh_s[tid] = s; sh_q[tid] = q;
    __syncthreads();
    for (int off = 128; off > 0; off >>= 1) {
        if (tid < off) { sh_s[tid] += sh_s[tid + off]; sh_q[tid] += sh_q[tid + off]; }
        __syncthreads();
    }
    if (tid == 0) { g_ps1[c * S1 + sp] = sh_s[0]; g_pq1[c * S1 + sp] = sh_q[0]; }
}

// ---------------- fold1 (finalize fused; also zeroes h-stat buckets) --------------
__global__ __launch_bounds__(256) void fold1_kernel(const float* __restrict__ w,
                                                    const float* __restrict__ bias,
                                                    const float* __restrict__ bg,
                                                    const float* __restrict__ bb) {
    __shared__ float sa[C1], sd[C1];
    __shared__ float sh[256];
    const int o = blockIdx.x, tid = threadIdx.x;
    if (blockIdx.x < (C2 * B_) / 256) {
        int idx = blockIdx.x * 256 + tid;
        g_s2[idx] = 0.f;
        g_q2[idx] = 0.f;
    }
    const float inv_n = 1.f / (float)(B_ * T_);
    #pragma unroll
    for (int k = tid; k < C1; k += 256) {
        float s = 0.f, q = 0.f;
        #pragma unroll
        for (int i = 0; i < S1; i++) { s += g_ps1[k * S1 + i]; q += g_pq1[k * S1 + i]; }
        float mean = s * inv_n;
        float var  = q * inv_n - mean * mean;
        float av = bg[k] * rsqrtf(var + EPSV);
        sa[k] = av;
        sd[k] = bb[k] - mean * av;
    }
    __syncthreads();
    float acc = 0.f;
    for (int k = tid; k < C1; k += 256) {
        float wv = w[(size_t)o * C1 + k];
        float wf = wv * sa[k];
        __nv_bfloat16 h = __float2bfloat16(wf);
        g_w1h[(size_t)o * C1 + k] = h;
        g_w1l[(size_t)o * C1 + k] = __float2bfloat16(wf - __bfloat162float(h));
        acc += wv * sd[k];
    }
    sh[tid] = acc;
    __syncthreads();
    for (int off = 128; off > 0; off >>= 1) {
        if (tid < off) sh[tid] += sh[tid + off];
        __syncthreads();
    }
    if (tid == 0) g_b1f[o] = bias[o] + sh[0];
}

// ---------------- fold2 (reads b-bucketed h stats) ----------------------------------
__global__ __launch_bounds__(256) void fold2_kernel(const float* __restrict__ w,
                                                    const float* __restrict__ bias,
                                                    const float* __restrict__ bg,
                                                    const float* __restrict__ bb) {
    __shared__ float sa[C2], sd[C2];
    __shared__ float sh[256];
    const int o = blockIdx.x, tid = threadIdx.x;
    const float inv_n = 1.f / (float)(B_ * T_);
    {
        float s = 0.f, q = 0.f;
        #pragma unroll
        for (int i = 0; i < B_; i++) { s += g_s2[tid * B_ + i]; q += g_q2[tid * B_ + i]; }
        float mean = s * inv_n;
        float var  = q * inv_n - mean * mean;
        float av = bg[tid] * rsqrtf(var + EPSV);
        sa[tid] = av;
        sd[tid] = bb[tid] - mean * av;
    }
    __syncthreads();
    float acc = 0.f;
    for (int k = tid; k < C2; k += 256) {
        float wv = w[(size_t)o * C2 + k];
        float wf = wv * sa[k];
        __nv_bfloat16 h = __float2bfloat16(wf);
        g_w2h[(size_t)o * C2 + k] = h;
        g_w2l[(size_t)o * C2 + k] = __float2bfloat16(wf - __bfloat162float(h));
        acc += wv * sd[k];
    }
    sh[tid] = acc;
    __syncthreads();
    for (int off = 128; off > 0; off >>= 1) {
        if (tid < off) sh[tid] += sh[tid + off];
        __syncthreads();
    }
    if (tid == 0) g_b2f[o] = bias[o] + sh[0];
}

// ---------------- GEMM1: cp.async 3-stage single-sync, mma bf16 3-term -------------
// Stage layout (32KB): Ah[0,8K) Al[8K,16K) Bh[16K,24K) Bl[24K,32K)
extern __shared__ char g1s[];

__device__ __forceinline__ void g1_issue(u32 sb, int it, int m0, int n0, int b, int tid) {
    const int k0 = it * BK;
    #pragma unroll
    for (int j = 0; j < 2; j++) {           // A: 512 uint4 each h/l
        int u = tid + j * 256;
        int row = u >> 2, c = u & 3;
        u32 dst = sb + row * 64 + ((c ^ ((row >> 1) & 3)) << 4);
        size_t src = (size_t)(m0 + row) * (C1 / 8) + (k0 >> 3) + c;
        cp16(dst,        (const uint4*)g_w1h + src);
        cp16(dst + 8192, (const uint4*)g_w1l + src);
    }
    #pragma unroll
    for (int j = 0; j < 2; j++) {           // B: 512 uint4 each h/l
        int u = tid + j * 256;
        int row = u >> 4, c = u & 15;
        u32 dst = sb + 16384 + row * 256 + ((c ^ (row & 7)) << 4);
        size_t src = (((size_t)(b * C1 + k0 + row)) * T_ + n0) / 8 + c;
        cp16(dst,        (const uint4*)g_xh + src);
        cp16(dst + 8192, (const uint4*)g_xl + src);
    }
    cpcommit();
}

__global__ __launch_bounds__(256, 2) void gemm1_kernel() {
    const int tid = threadIdx.x, lane = tid & 31, wid = tid >> 5;
    const int b = blockIdx.z, m0 = blockIdx.y * BM, n0 = blockIdx.x * BN;
    const int wm = (wid & 3) * 32, wn = (wid >> 2) * 64;
    const u32 sb0 = smem_u32(g1s);

    float acc[2][8][4];
    #pragma unroll
    for (int mi = 0; mi < 2; mi++)
        #pragma unroll
        for (int nj = 0; nj < 8; nj++)
            #pragma unroll
            for (int r = 0; r < 4; r++) acc[mi][nj][r] = 0.f;

    g1_issue(sb0,            0, m0, n0, b, tid);
    g1_issue(sb0 + G1_STAGE, 1, m0, n0, b, tid);

    #pragma unroll 1
    for (int it = 0; it < KIT; it++) {
        if (it < KIT - 1) asm volatile("cp.async.wait_group 1;" ::: "memory");
        else              asm volatile("cp.async.wait_group 0;" ::: "memory");
        __syncthreads();
        if (it + 2 < KIT) {
            int sl = it + 2 - ((it + 2) / 3) * 3;
            g1_issue(sb0 + sl * G1_STAGE, it + 2, m0, n0, b, tid);
        }
        const u32 Abase = sb0 + (it - (it / 3) * 3) * G1_STAGE;
        #pragma unroll
        for (int ks = 0; ks < 2; ks++) {
            u32 ah[2][4], al[2][4];
            #pragma unroll
            for (int mi = 0; mi < 2; mi++) {
                int ml = wm + mi * 16 + (lane & 15);
                int kk = ks * 16 + (lane >> 4) * 8;
                u32 a_addr = Abase + ml * 64 + (((kk >> 3) ^ ((ml >> 1) & 3)) << 4);
                ldsm4(ah[mi], a_addr);
                ldsm4(al[mi], a_addr + 8192);
            }
            const int mat = lane >> 3, rr = lane & 7;
            #pragma unroll
            for (int nb = 0; nb < 4; nb++) {
                int kk = ks * 16 + (mat & 1) * 8 + rr;
                int nn = wn + nb * 16 + (mat >> 1) * 8;
                u32 b_addr = Abase + 16384 + kk * 256 + (((nn >> 3) ^ (kk & 7)) << 4);
                u32 bh[4], bl[4];
                ldsm4t(bh, b_addr);
                ldsm4t(bl, b_addr + 8192);
                #pragma unroll
                for (int mi = 0; mi < 2; mi++) {
                    mma16816(acc[mi][2*nb],     ah[mi], bh);
                    mma16816(acc[mi][2*nb],     ah[mi], bl);
                    mma16816(acc[mi][2*nb],     al[mi], bh);
                    mma16816(acc[mi][2*nb + 1], ah[mi], bh + 2);
                    mma16816(acc[mi][2*nb + 1], ah[mi], bl + 2);
                    mma16816(acc[mi][2*nb + 1], al[mi], bh + 2);
                }
            }
        }
    }

    // epilogue: v = relu(acc + bias); split -> g_hh/g_hl; fused h-stats (s,q)
    const int g = lane >> 2, q = lane & 3;
    #pragma unroll
    for (int mi = 0; mi < 2; mi++) {
        #pragma unroll
        for (int rw = 0; rw < 2; rw++) {
            const int m = m0 + wm + mi * 16 + g + rw * 8;
            const float bias = g_b1f[m];
            size_t rowu = (((size_t)b * C2 + m) * T_ + n0 + wn) / 2;
            float s = 0.f, qs = 0.f;
            #pragma unroll
            for (int nj = 0; nj < 8; nj++) {
                float v0 = fmaxf(acc[mi][nj][rw * 2 + 0] + bias, 0.f);
                float v1 = fmaxf(acc[mi][nj][rw * 2 + 1] + bias, 0.f);
                s  += v0 + v1;
                qs += v0 * v0 + v1 * v1;
                u32 h, l;
                split2(v0, v1, h, l);
                g_hh[rowu + nj * 4 + q] = h;
                g_hl[rowu + nj * 4 + q] = l;
            }
            // reduce (s,qs) across the 4 lanes (q=0..3) owning this row
            s  += __shfl_down_sync(0xffffffffu, s, 2);
            s  += __shfl_down_sync(0xffffffffu, s, 1);
            qs += __shfl_down_sync(0xffffffffu, qs, 2);
            qs += __shfl_down_sync(0xffffffffu, qs, 1);
            if (q == 0) {
                atomicAdd(&g_s2[m * B_ + b], s);
                atomicAdd(&g_q2[m * B_ + b], qs);
            }
        }
    }
}

// ---------------- GEMM2: cp.async 3-stage single-sync, mma bf16 3-term -------------
extern __shared__ char g2s[];

__device__ __forceinline__ void g2_issue(u32 sb, int it, int n0, int b, int tid) {
    const int k0 = it * 32;
    {
        int row = tid >> 2, c = tid & 3;
        u32 dst = sb + row * 64 + ((c ^ ((row >> 1) & 3)) << 4);
        size_t src = (size_t)row * (C2 / 8) + (k0 >> 3) + c;
        cp16(dst,        (const uint4*)g_w2h + src);
        cp16(dst + 4096, (const uint4*)g_w2l + src);
    }
    #pragma unroll
    for (int j = 0; j < 2; j++) {
        int u = tid + j * 256;
        int row = u >> 4, c = u & 15;
        u32 dst = sb + 8192 + row * 256 + ((c ^ (row & 7)) << 4);
        size_t src = (((size_t)(b * C2 + k0 + row)) * T_ + n0) / 8 + c;
        cp16(dst,        (const uint4*)g_hh + src);
        cp16(dst + 8192, (const uint4*)g_hl + src);
    }
    cpcommit();
}

__global__ __launch_bounds__(256, 2) void gemm2_kernel(float* __restrict__ out) {
    const int tid = threadIdx.x, lane = tid & 31, wid = tid >> 5;
    const int b = blockIdx.z, n0 = blockIdx.x * 128;
    const int wm = (wid & 1) * 32, wn = (wid >> 1) * 32;
    const u32 sb0 = smem_u32(g2s);

    float acc[2][4][4];
    #pragma unroll
    for (int mi = 0; mi < 2; mi++)
        #pragma unroll
        for (int nj = 0; nj < 4; nj++)
            #pragma unroll
            for (int r = 0; r < 4; r++) acc[mi][nj][r] = 0.f;

    g2_issue(sb0,            0, n0, b, tid);
    g2_issue(sb0 + G2_STAGE, 1, n0, b, tid);

    #pragma unroll 1
    for (int it = 0; it < KIT2; it++) {
        if (it < KIT2 - 1) asm volatile("cp.async.wait_group 1;" ::: "memory");
        else               asm volatile("cp.async.wait_group 0;" ::: "memory");
        __syncthreads();
        if (it + 2 < KIT2) {
            int sl = it + 2 - ((it + 2) / 3) * 3;
            g2_issue(sb0 + sl * G2_STAGE, it + 2, n0, b, tid);
        }
        const u32 Bbase = sb0 + (it - (it / 3) * 3) * G2_STAGE;
        #pragma unroll
        for (int ks = 0; ks < 2; ks++) {
            u32 ah[2][4], al[2][4];
            #pragma unroll
            for (int mi = 0; mi < 2; mi++) {
                int ml = wm + mi * 16 + (lane & 15);
                int kk = ks * 16 + (lane >> 4) * 8;
                u32 a_addr = Bbase + ml * 64 + (((kk >> 3) ^ ((ml >> 1) & 3)) << 4);
                ldsm4(ah[mi], a_addr);
                ldsm4(al[mi], a_addr + 4096);
            }
            const int mat = lane >> 3, rr = lane & 7;
            #pragma unroll
            for (int nbk = 0; nbk < 2; nbk++) {
                int kk = ks * 16 + (mat & 1) * 8 + rr;
                int nn = wn + nbk * 16 + (mat >> 1) * 8;
                u32 b_addr = Bbase + 8192 + kk * 256 + (((nn >> 3) ^ (kk & 7)) << 4);
                u32 bh[4], bl[4];
                ldsm4t(bh, b_addr);
                ldsm4t(bl, b_addr + 8192);
                #pragma unroll
                for (int mi = 0; mi < 2; mi++) {
                    mma16816(acc[mi][2*nbk],     ah[mi], bh);
                    mma16816(acc[mi][2*nbk],     ah[mi], bl);
                    mma16816(acc[mi][2*nbk],     al[mi], bh);
                    mma16816(acc[mi][2*nbk + 1], ah[mi], bh + 2);
                    mma16816(acc[mi][2*nbk + 1], ah[mi], bl + 2);
                    mma16816(acc[mi][2*nbk + 1], al[mi], bh + 2);
                }
            }
        }
    }

    const int g = lane >> 2, q = lane & 3;
    #pragma unroll
    for (int mi = 0; mi < 2; mi++) {
        #pragma unroll
        for (int rw = 0; rw < 2; rw++) {
            const int o = wm + mi * 16 + g + rw * 8;
            const float bias = g_b2f[o];
            const size_t base = (o < 32)
                ? ((size_t)b * 32 * T_ + (size_t)o * T_)
                : (MUHALF + (size_t)b * 32 * T_ + (size_t)(o - 32) * T_);
            #pragma unroll
            for (int nj = 0; nj < 4; nj++) {
                float2 v;
                v.x = acc[mi][nj][rw * 2 + 0] + bias;
                v.y = acc[mi][nj][rw * 2 + 1] + bias;
                *(float2*)(out + base + n0 + wn + nj * 8 + q * 2) = v;
            }
        }
    }
}

// ---------------- launcher -----------------------------------------------------------
extern "C" void kernel_launch(void* const* d_in, const int* in_sizes, int n_in,
                              void* d_out, int out_size) {
    const float* x     = (const float*)d_in[0];
    const float* bn1_g = (const float*)d_in[1];
    const float* bn1_b = (const float*)d_in[2];
    const float* w1    = (const float*)d_in[3];
    const float* b1    = (const float*)d_in[4];
    const float* bn2_g = (const float*)d_in[5];
    const float* bn2_b = (const float*)d_in[6];
    const float* w2    = (const float*)d_in[7];
    const float* b2    = (const float*)d_in[8];
    float* out = (float*)d_out;

    cudaFuncSetAttribute(gemm1_kernel, cudaFuncAttributeMaxDynamicSharedMemorySize, G1_SMEM);
    cudaFuncSetAttribute(gemm2_kernel, cudaFuncAttributeMaxDynamicSharedMemorySize, G2_SMEM);

    stats1_split_kernel<<<dim3(C1, S1), 256>>>(x);
    fold1_kernel<<<C2, 256>>>(w1, b1, bn1_g, bn1_b);
    gemm1_kernel<<<dim3(T_ / BN, C2 / BM, B_), 256, G1_SMEM>>>();
    fold2_kernel<<<C3, 256>>>(w2, b2, bn2_g, bn2_b);
    gemm2_kernel<<<dim3(T_ / 128, 1, B_), 256, G2_SMEM>>>(out);
}